// round 14
// baseline (speedup 1.0000x reference)
#include <cuda_runtime.h>
#include <cuda_fp16.h>
#include <cstdint>

// EnhancedMoEModel: out[b] = sum_e probs[b,e] * sigmoid( relu( relu(x W1e + b1e) W2e + b2e ) W3e + b3e )
// B=524288, D=32, H=64, H2=32, E=8, O=1.
//
// R13: expert-per-warp with ALL weights pinned in registers (~81 regs/expert).
// Inner loop has ZERO shared-memory and zero weight loads: HMMA + HMNMX2 + 8 x-LDGs.
// Experts combined via global f32 atomicAdd into a memset-zeroed out buffer.
// f16 end-to-end (R10 math): D-fragment of f16-acc mma == next A-fragment.

#define NUM_E 8

__device__ __forceinline__ uint32_t packh(float lo, float hi) {
    __half2 h = __floats2half2_rn(lo, hi);
    return *reinterpret_cast<uint32_t*>(&h);
}

__device__ __forceinline__ uint32_t hrelu(uint32_t v) {
    __half2 h = *reinterpret_cast<__half2*>(&v);
    h = __hmax2(h, __floats2half2_rn(0.f, 0.f));
    return *reinterpret_cast<uint32_t*>(&h);
}

// f16-accumulate mma: D (2 regs, f16x2) layout == next-layer A-fragment layout.
__device__ __forceinline__ void mma_f16(uint32_t& d0, uint32_t& d1,
                                        const uint32_t a[4], uint32_t b0, uint32_t b1) {
    asm volatile(
        "mma.sync.aligned.m16n8k16.row.col.f16.f16.f16.f16 "
        "{%0,%1}, {%2,%3,%4,%5}, {%6,%7}, {%0,%1};\n"
        : "+r"(d0), "+r"(d1)
        : "r"(a[0]), "r"(a[1]), "r"(a[2]), "r"(a[3]), "r"(b0), "r"(b1));
}

__global__ void __launch_bounds__(128, 4)
moe_kernel(const float* __restrict__ x,
           const float* __restrict__ probs,
           const float* __restrict__ W1, const float* __restrict__ b1,
           const float* __restrict__ W2, const float* __restrict__ b2,
           const float* __restrict__ W3, const float* __restrict__ b3,
           float* __restrict__ out, int NT16)
{
    const int lane = threadIdx.x & 31;
    const int c  = lane & 3;      // quad column index
    const int rq = lane >> 2;     // row within 8-row group
    const int wid = threadIdx.x >> 5;              // 0..3
    const int e = ((blockIdx.x & 1) << 2) | wid;   // expert owned by this warp (fixed)
    const int tile0 = blockIdx.x >> 1;
    const int tstride = gridDim.x >> 1;

    // ---- one-time: gather this expert's weights into registers (mma B-fragment order) ----
    // B fragment (m16n8k16,col), lane(cc=c, nn=rq): b0={B[k0][n],B[k0+1][n]}, b1={B[k0+8][n],B[k0+9][n]}
    const int cc = c, nn = rq;

    uint4 W1f[8];                     // [j]: {b0(s0), b1(s0), b0(s1), b1(s1)}, col = 8j+nn
    {
        const float* w1 = W1 + (size_t)e * 32 * 64;
        #pragma unroll
        for (int j = 0; j < 8; j++) {
            int col = 8 * j + nn;
            int k0 = 2 * cc;
            W1f[j].x = packh(w1[(k0     ) * 64 + col], w1[(k0 +  1) * 64 + col]);
            W1f[j].y = packh(w1[(k0 +  8) * 64 + col], w1[(k0 +  9) * 64 + col]);
            W1f[j].z = packh(w1[(k0 + 16) * 64 + col], w1[(k0 + 17) * 64 + col]);
            W1f[j].w = packh(w1[(k0 + 24) * 64 + col], w1[(k0 + 25) * 64 + col]);
        }
    }
    uint4 W2a[4], W2b[4];             // [j2]: s2={0,1} and s2={2,3}, col = 8*j2+nn
    {
        const float* w2 = W2 + (size_t)e * 64 * 32;
        #pragma unroll
        for (int j2 = 0; j2 < 4; j2++) {
            int col = 8 * j2 + nn;
            #pragma unroll
            for (int s2 = 0; s2 < 4; s2++) {
                int k0 = 16 * s2 + 2 * cc;
                uint32_t v0 = packh(w2[(k0    ) * 32 + col], w2[(k0 + 1) * 32 + col]);
                uint32_t v1 = packh(w2[(k0 + 8) * 32 + col], w2[(k0 + 9) * 32 + col]);
                if      (s2 == 0) { W2a[j2].x = v0; W2a[j2].y = v1; }
                else if (s2 == 1) { W2a[j2].z = v0; W2a[j2].w = v1; }
                else if (s2 == 2) { W2b[j2].x = v0; W2b[j2].y = v1; }
                else              { W2b[j2].z = v0; W2b[j2].w = v1; }
            }
        }
    }
    uint4 W3v = make_uint4(0u, 0u, 0u, 0u);   // L3 B: w3 in col 0, zeros elsewhere
    if (nn == 0) {
        const float* w3 = W3 + e * 32;
        W3v.x = packh(w3[2 * cc],      w3[2 * cc + 1]);
        W3v.y = packh(w3[2 * cc + 8],  w3[2 * cc + 9]);
        W3v.z = packh(w3[2 * cc + 16], w3[2 * cc + 17]);
        W3v.w = packh(w3[2 * cc + 24], w3[2 * cc + 25]);
    }
    uint32_t b1h[8];
    #pragma unroll
    for (int j = 0; j < 8; j++) {
        int col = 8 * j + 2 * c;
        b1h[j] = packh(b1[e * 64 + col], b1[e * 64 + col + 1]);
    }
    uint32_t b2h[4];
    #pragma unroll
    for (int j2 = 0; j2 < 4; j2++) {
        int col = 8 * j2 + 2 * c;
        b2h[j2] = packh(b2[e * 32 + col], b2[e * 32 + col + 1]);
    }
    const uint32_t b3h = packh(b3[e], b3[e]);

    // ---- stride loop over 16-row tiles; this warp applies expert e to each ----
    for (int tile = tile0; tile < NT16; tile += tstride) {
        const int rowbase = tile << 4;

        // x A-fragments (f32 -> f16x2 on the fly); all 4 warps in block read same lines -> L1 hits
        uint32_t xa[2][4];
        {
            const float* xr0 = x + (size_t)(rowbase + rq) * 32;
            const float* xr1 = xr0 + 8 * 32;
            #pragma unroll
            for (int s = 0; s < 2; s++) {
                const int col = 16 * s + 2 * c;
                float2 v00 = *reinterpret_cast<const float2*>(xr0 + col);
                float2 v10 = *reinterpret_cast<const float2*>(xr1 + col);
                float2 v01 = *reinterpret_cast<const float2*>(xr0 + col + 8);
                float2 v11 = *reinterpret_cast<const float2*>(xr1 + col + 8);
                xa[s][0] = packh(v00.x, v00.y);
                xa[s][1] = packh(v10.x, v10.y);
                xa[s][2] = packh(v01.x, v01.y);
                xa[s][3] = packh(v11.x, v11.y);
            }
        }

        // layer 1: [16,32] @ [32,64] — weights from registers, no memory ops
        uint32_t ha[4][4];
        #pragma unroll
        for (int j = 0; j < 8; j++) {
            uint32_t d0 = b1h[j], d1 = b1h[j];
            mma_f16(d0, d1, xa[0], W1f[j].x, W1f[j].y);
            mma_f16(d0, d1, xa[1], W1f[j].z, W1f[j].w);
            ha[j >> 1][(j & 1) * 2 + 0] = hrelu(d0);
            ha[j >> 1][(j & 1) * 2 + 1] = hrelu(d1);
        }

        // layer 2: [16,64] @ [64,32]
        uint32_t la[2][4];
        #pragma unroll
        for (int j2 = 0; j2 < 4; j2++) {
            uint32_t d0 = b2h[j2], d1 = b2h[j2];
            mma_f16(d0, d1, ha[0], W2a[j2].x, W2a[j2].y);
            mma_f16(d0, d1, ha[1], W2a[j2].z, W2a[j2].w);
            mma_f16(d0, d1, ha[2], W2b[j2].x, W2b[j2].y);
            mma_f16(d0, d1, ha[3], W2b[j2].z, W2b[j2].w);
            la[j2 >> 1][(j2 & 1) * 2 + 0] = hrelu(d0);
            la[j2 >> 1][(j2 & 1) * 2 + 1] = hrelu(d1);
        }

        // layer 3 as HMMA: z = relu(h2) @ [w3 | 0...]; z in lo halves, valid at c==0
        uint32_t d30 = b3h, d31 = b3h;
        mma_f16(d30, d31, la[0], W3v.x, W3v.y);
        mma_f16(d30, d31, la[1], W3v.z, W3v.w);

        if (c == 0) {
            float z0 = __low2float(*reinterpret_cast<__half2*>(&d30));
            float z1 = __low2float(*reinterpret_cast<__half2*>(&d31));
            float s0 = 1.f / (1.f + __expf(-z0));
            float s1 = 1.f / (1.f + __expf(-z1));
            float p0 = probs[(size_t)(rowbase + rq) * NUM_E + e];
            float p1 = probs[(size_t)(rowbase + 8 + rq) * NUM_E + e];
            atomicAdd(&out[rowbase + rq],     s0 * p0);
            atomicAdd(&out[rowbase + 8 + rq], s1 * p1);
        }
    }
}

extern "C" void kernel_launch(void* const* d_in, const int* in_sizes, int n_in,
                              void* d_out, int out_size) {
    const float* x     = (const float*)d_in[0];
    const float* probs = (const float*)d_in[1];
    const float* W1    = (const float*)d_in[2];
    const float* b1    = (const float*)d_in[3];
    const float* W2    = (const float*)d_in[4];
    const float* b2    = (const float*)d_in[5];
    const float* W3    = (const float*)d_in[6];
    const float* b3    = (const float*)d_in[7];
    float* out = (float*)d_out;

    const int B    = in_sizes[0] / 32;
    const int NT16 = B / 16;   // 32768 row-tiles of 16 rows

    // out accumulates across experts -> zero it first (graph-capturable memset)
    cudaMemsetAsync(out, 0, (size_t)out_size * sizeof(float), 0);

    // 592 blocks x 4 warps; block pair (2t,2t+1) covers experts 0-3 / 4-7 of the
    // same tile stream. Each warp keeps ONE expert's weights in registers.
    moe_kernel<<<592, 128>>>(x, probs, W1, b1, W2, b2, W3, b3, out, NT16);
}

// round 15
// speedup vs baseline: 1.4082x; 1.4082x over previous
#include <cuda_runtime.h>
#include <cuda_fp16.h>
#include <cstdint>

// EnhancedMoEModel: out[b] = sum_e probs[b,e] * sigmoid( relu( relu(x W1e + b1e) W2e + b2e ) W3e + b3e )
// B=524288, D=32, H=64, H2=32, E=8, O=1.
//
// R14 = R13 concept (expert-per-warp, weights in registers, zero weight-LDS inner
// loop) with the register overflow fixed:
//  - biases live in a tiny static smem table, re-read INSIDE the tile loop via
//    asm-volatile LDS.128 (3 per tile) so they never occupy persistent registers
//  - L3 fused per k-step (no la[] array)
//  - one 256-thread CTA = 8 warps = 8 experts, same tile stream (x L1-hot)
// Experts combine via global f32 atomicAdd into memset-zeroed out.

#define NUM_E 8

__device__ __forceinline__ uint32_t packh(float lo, float hi) {
    __half2 h = __floats2half2_rn(lo, hi);
    return *reinterpret_cast<uint32_t*>(&h);
}

__device__ __forceinline__ uint32_t hrelu(uint32_t v) {
    __half2 h = *reinterpret_cast<__half2*>(&v);
    h = __hmax2(h, __floats2half2_rn(0.f, 0.f));
    return *reinterpret_cast<uint32_t*>(&h);
}

// f16-accumulate mma: D (2 regs, f16x2) layout == next-layer A-fragment layout.
__device__ __forceinline__ void mma_f16(uint32_t& d0, uint32_t& d1,
                                        const uint32_t a[4], uint32_t b0, uint32_t b1) {
    asm volatile(
        "mma.sync.aligned.m16n8k16.row.col.f16.f16.f16.f16 "
        "{%0,%1}, {%2,%3,%4,%5}, {%6,%7}, {%0,%1};\n"
        : "+r"(d0), "+r"(d1)
        : "r"(a[0]), "r"(a[1]), "r"(a[2]), "r"(a[3]), "r"(b0), "r"(b1));
}

__global__ void __launch_bounds__(256, 2)
moe_kernel(const float* __restrict__ x,
           const float* __restrict__ probs,
           const float* __restrict__ W1, const float* __restrict__ b1,
           const float* __restrict__ W2, const float* __restrict__ b2,
           const float* __restrict__ W3, const float* __restrict__ b3,
           float* __restrict__ out, int NT16)
{
    __shared__ uint32_t sB1h[8][4][8];   // [e][c][j]  f16x2 bias pairs, LDS.128-able
    __shared__ uint32_t sB2h[8][4][4];   // [e][c][j2]

    const int tid  = threadIdx.x;
    const int lane = tid & 31;
    const int c    = lane & 3;     // quad column index
    const int rq   = lane >> 2;    // row within 8-row group
    const int e    = tid >> 5;     // warp id == expert id (8 warps)

    // ---- bias tables into smem (packed so one LDS.128 covers 4 j's) ----
    {
        int ee = tid >> 5, cc2 = (tid >> 3) & 3, jj = tid & 7;
        sB1h[ee][cc2][jj] = packh(b1[ee * 64 + 8 * jj + 2 * cc2],
                                  b1[ee * 64 + 8 * jj + 2 * cc2 + 1]);
        if (tid < 128) {
            int e2 = tid >> 4, c2 = (tid >> 2) & 3, j2 = tid & 3;
            sB2h[e2][c2][j2] = packh(b2[e2 * 32 + 8 * j2 + 2 * c2],
                                     b2[e2 * 32 + 8 * j2 + 2 * c2 + 1]);
        }
    }

    // ---- gather this expert's weights into registers (mma B-fragment order) ----
    // lane (cc=c, nn=rq): b0={B[k0][n],B[k0+1][n]}, b1={B[k0+8][n],B[k0+9][n]}
    const int cc = c, nn = rq;

    uint4 W1f[8];                     // [j]: {b0(s0), b1(s0), b0(s1), b1(s1)}, col = 8j+nn
    {
        const float* w1 = W1 + (size_t)e * 32 * 64;
        #pragma unroll
        for (int j = 0; j < 8; j++) {
            int col = 8 * j + nn;
            int k0 = 2 * cc;
            W1f[j].x = packh(w1[(k0     ) * 64 + col], w1[(k0 +  1) * 64 + col]);
            W1f[j].y = packh(w1[(k0 +  8) * 64 + col], w1[(k0 +  9) * 64 + col]);
            W1f[j].z = packh(w1[(k0 + 16) * 64 + col], w1[(k0 + 17) * 64 + col]);
            W1f[j].w = packh(w1[(k0 + 24) * 64 + col], w1[(k0 + 25) * 64 + col]);
        }
    }
    uint4 W2a[4], W2b[4];             // [j2]: s2={0,1} and s2={2,3}, col = 8*j2+nn
    {
        const float* w2 = W2 + (size_t)e * 64 * 32;
        #pragma unroll
        for (int j2 = 0; j2 < 4; j2++) {
            int col = 8 * j2 + nn;
            #pragma unroll
            for (int s2 = 0; s2 < 4; s2++) {
                int k0 = 16 * s2 + 2 * cc;
                uint32_t v0 = packh(w2[(k0    ) * 32 + col], w2[(k0 + 1) * 32 + col]);
                uint32_t v1 = packh(w2[(k0 + 8) * 32 + col], w2[(k0 + 9) * 32 + col]);
                if      (s2 == 0) { W2a[j2].x = v0; W2a[j2].y = v1; }
                else if (s2 == 1) { W2a[j2].z = v0; W2a[j2].w = v1; }
                else if (s2 == 2) { W2b[j2].x = v0; W2b[j2].y = v1; }
                else              { W2b[j2].z = v0; W2b[j2].w = v1; }
            }
        }
    }
    uint4 W3v = make_uint4(0u, 0u, 0u, 0u);   // L3 B: w3 in col 0, zeros elsewhere
    if (nn == 0) {
        const float* w3 = W3 + e * 32;
        W3v.x = packh(w3[2 * cc],      w3[2 * cc + 1]);
        W3v.y = packh(w3[2 * cc + 8],  w3[2 * cc + 9]);
        W3v.z = packh(w3[2 * cc + 16], w3[2 * cc + 17]);
        W3v.w = packh(w3[2 * cc + 24], w3[2 * cc + 25]);
    }
    const uint32_t b3h = packh(b3[e], b3[e]);

    __syncthreads();

    const uint32_t sb1a = (uint32_t)__cvta_generic_to_shared(&sB1h[e][c][0]);
    const uint32_t sb2a = (uint32_t)__cvta_generic_to_shared(&sB2h[e][c][0]);

    // ---- tile loop: all 8 warps (experts) of the CTA walk the same 16-row tiles ----
    for (int tile = blockIdx.x; tile < NT16; tile += gridDim.x) {
        const int rowbase = tile << 4;

        // x A-fragments (f32 -> f16x2); 8 warps read the same lines -> L1 hits
        uint32_t xa[2][4];
        {
            const float* xr0 = x + (size_t)(rowbase + rq) * 32;
            const float* xr1 = xr0 + 8 * 32;
            #pragma unroll
            for (int s = 0; s < 2; s++) {
                const int col = 16 * s + 2 * c;
                float2 v00 = *reinterpret_cast<const float2*>(xr0 + col);
                float2 v10 = *reinterpret_cast<const float2*>(xr1 + col);
                float2 v01 = *reinterpret_cast<const float2*>(xr0 + col + 8);
                float2 v11 = *reinterpret_cast<const float2*>(xr1 + col + 8);
                xa[s][0] = packh(v00.x, v00.y);
                xa[s][1] = packh(v10.x, v10.y);
                xa[s][2] = packh(v01.x, v01.y);
                xa[s][3] = packh(v11.x, v11.y);
            }
        }

        // biases re-read from smem each tile (asm volatile: kept OUT of registers
        // across the loop, which is what keeps us under the 128-reg cap)
        uint32_t bj[8], b2j[4];
        asm volatile("ld.shared.v4.u32 {%0,%1,%2,%3}, [%4];"
                     : "=r"(bj[0]), "=r"(bj[1]), "=r"(bj[2]), "=r"(bj[3]) : "r"(sb1a));
        asm volatile("ld.shared.v4.u32 {%0,%1,%2,%3}, [%4];"
                     : "=r"(bj[4]), "=r"(bj[5]), "=r"(bj[6]), "=r"(bj[7]) : "r"(sb1a + 16));
        asm volatile("ld.shared.v4.u32 {%0,%1,%2,%3}, [%4];"
                     : "=r"(b2j[0]), "=r"(b2j[1]), "=r"(b2j[2]), "=r"(b2j[3]) : "r"(sb2a));

        // layer 1: [16,32] @ [32,64] — weights from registers, zero memory ops
        uint32_t ha[4][4];
        #pragma unroll
        for (int j = 0; j < 8; j++) {
            uint32_t d0 = bj[j], d1 = bj[j];
            mma_f16(d0, d1, xa[0], W1f[j].x, W1f[j].y);
            mma_f16(d0, d1, xa[1], W1f[j].z, W1f[j].w);
            ha[j >> 1][(j & 1) * 2 + 0] = hrelu(d0);
            ha[j >> 1][(j & 1) * 2 + 1] = hrelu(d1);
        }

        // layers 2+3 fused per k-step (no persistent la[] array)
        uint32_t d30 = b3h, d31 = b3h;
        #pragma unroll
        for (int s3 = 0; s3 < 2; s3++) {
            uint32_t lf[4];
            #pragma unroll
            for (int h = 0; h < 2; h++) {
                const int j2 = 2 * s3 + h;
                uint32_t d0 = b2j[j2], d1 = b2j[j2];
                mma_f16(d0, d1, ha[0], W2a[j2].x, W2a[j2].y);
                mma_f16(d0, d1, ha[1], W2a[j2].z, W2a[j2].w);
                mma_f16(d0, d1, ha[2], W2b[j2].x, W2b[j2].y);
                mma_f16(d0, d1, ha[3], W2b[j2].z, W2b[j2].w);
                lf[h * 2 + 0] = hrelu(d0);
                lf[h * 2 + 1] = hrelu(d1);
            }
            const uint32_t B0 = (s3 == 0) ? W3v.x : W3v.z;
            const uint32_t B1 = (s3 == 0) ? W3v.y : W3v.w;
            mma_f16(d30, d31, lf, B0, B1);
        }

        // epilogue: z in lo halves (valid at c==0); sigmoid, weight, atomic combine
        if (c == 0) {
            float z0 = __low2float(*reinterpret_cast<__half2*>(&d30));
            float z1 = __low2float(*reinterpret_cast<__half2*>(&d31));
            float s0 = 1.f / (1.f + __expf(-z0));
            float s1 = 1.f / (1.f + __expf(-z1));
            float p0 = probs[(size_t)(rowbase + rq) * NUM_E + e];
            float p1 = probs[(size_t)(rowbase + 8 + rq) * NUM_E + e];
            atomicAdd(&out[rowbase + rq],     s0 * p0);
            atomicAdd(&out[rowbase + 8 + rq], s1 * p1);
        }
    }
}

extern "C" void kernel_launch(void* const* d_in, const int* in_sizes, int n_in,
                              void* d_out, int out_size) {
    const float* x     = (const float*)d_in[0];
    const float* probs = (const float*)d_in[1];
    const float* W1    = (const float*)d_in[2];
    const float* b1    = (const float*)d_in[3];
    const float* W2    = (const float*)d_in[4];
    const float* b2    = (const float*)d_in[5];
    const float* W3    = (const float*)d_in[6];
    const float* b3    = (const float*)d_in[7];
    float* out = (float*)d_out;

    const int B    = in_sizes[0] / 32;
    const int NT16 = B / 16;   // 32768 row-tiles of 16 rows

    // out accumulates across experts -> zero it first (graph-capturable memset)
    cudaMemsetAsync(out, 0, (size_t)out_size * sizeof(float), 0);

    // 296 CTAs (2/SM) x 8 warps; each warp owns one expert, CTA walks tile stream
    moe_kernel<<<296, 256>>>(x, probs, W1, b1, W2, b2, W3, b3, out, NT16);
}

// round 17
// speedup vs baseline: 1.8332x; 1.3018x over previous
#include <cuda_runtime.h>
#include <cuda_fp16.h>
#include <cstdint>

// EnhancedMoEModel: out[b] = sum_e probs[b,e] * sigmoid( relu( relu(x W1e + b1e) W2e + b2e ) W3e + b3e )
// B=524288, D=32, H=64, H2=32, E=8, O=1.
//
// R15 = R10 (best, 102.4us) + separate-C first-mma: mma.sync's C operand reads the
// bias register directly, eliminating the 2 accumulator-init MOVs per chain that the
// inout (+r) asm forced (416 MOVs per 32-row tile, ~23% of the issue stream).
// Numerics bit-identical to R10. Everything else unchanged.

#define NUM_E 8
// sW1 2048 u4 + sW2 2048 u4 + sW3f 256 u4 + sB1h 256 u32 + sB2h 128 u32 + sB3h 8 u32
#define SMEM_BYTES (2048*16 + 2048*16 + 256*16 + 256*4 + 128*4 + 8*4)

__device__ __forceinline__ uint32_t packh(float lo, float hi) {
    __half2 h = __floats2half2_rn(lo, hi);
    return *reinterpret_cast<uint32_t*>(&h);
}

__device__ __forceinline__ uint32_t hrelu(uint32_t v) {
    __half2 h = *reinterpret_cast<__half2*>(&v);
    h = __hmax2(h, __floats2half2_rn(0.f, 0.f));
    return *reinterpret_cast<uint32_t*>(&h);
}

// accumulating mma (chain continuation): D += A*B
__device__ __forceinline__ void mma_f16(uint32_t& d0, uint32_t& d1,
                                        const uint32_t a[4], uint32_t b0, uint32_t b1) {
    asm volatile(
        "mma.sync.aligned.m16n8k16.row.col.f16.f16.f16.f16 "
        "{%0,%1}, {%2,%3,%4,%5}, {%6,%7}, {%0,%1};\n"
        : "+r"(d0), "+r"(d1)
        : "r"(a[0]), "r"(a[1]), "r"(a[2]), "r"(a[3]), "r"(b0), "r"(b1));
}

// chain-start mma with separate C operand: D = A*B + C  (no accumulator-init MOVs)
__device__ __forceinline__ void mma_f16_init(uint32_t& d0, uint32_t& d1,
                                             const uint32_t a[4], uint32_t b0, uint32_t b1,
                                             uint32_t c0, uint32_t c1) {
    asm volatile(
        "mma.sync.aligned.m16n8k16.row.col.f16.f16.f16.f16 "
        "{%0,%1}, {%2,%3,%4,%5}, {%6,%7}, {%8,%9};\n"
        : "=r"(d0), "=r"(d1)
        : "r"(a[0]), "r"(a[1]), "r"(a[2]), "r"(a[3]), "r"(b0), "r"(b1),
          "r"(c0), "r"(c1));
}

__global__ void __launch_bounds__(256, 2)
moe_kernel(const float* __restrict__ x,
           const float* __restrict__ probs,
           const float* __restrict__ W1, const float* __restrict__ b1,
           const float* __restrict__ W2, const float* __restrict__ b2,
           const float* __restrict__ W3, const float* __restrict__ b3,
           float* __restrict__ out, int NT32)
{
    extern __shared__ unsigned char smem_raw[];
    uint4*    sW1  = reinterpret_cast<uint4*>(smem_raw);        // 2048: [e][j][lane] = {B(s0), B(s1)}
    uint4*    sW2  = sW1 + 2048;                                // 2048: [e][j2][half][lane]
    uint4*    sW3f = sW2 + 2048;                                // 256: [e][lane] L3 B-frags
    uint32_t* sB1h = reinterpret_cast<uint32_t*>(sW3f + 256);   // 256: [e][j][c] = f16x2 bias pair
    uint32_t* sB2h = sB1h + 256;                                // 128: [e][j2][c]
    uint32_t* sB3h = sB2h + 128;                                // 8:   [e] = f16x2 {b3,b3}

    // ---- one-time weight pre-swizzle into mma B-fragment order (f16x2 pairs) ----
    // B fragment (m16n8k16, col): lane t: b0={B[2c][n],B[2c+1][n]}, b1={B[2c+8][n],B[2c+9][n]},
    // c=t%4, n=t/4. k-step s adds 16 to k.
    for (int idx = threadIdx.x; idx < 2048; idx += blockDim.x) {
        int lanei = idx & 31, j = (idx >> 5) & 7, e = idx >> 8;
        int cc = lanei & 3, nn = lanei >> 2;
        int col = 8 * j + nn;
        const float* base = W1 + (size_t)e * 32 * 64;
        #pragma unroll
        for (int s = 0; s < 2; s++) {
            int k0 = 16 * s + 2 * cc;
            float v00 = base[(k0    ) * 64 + col];
            float v01 = base[(k0 + 1) * 64 + col];
            float v10 = base[(k0 + 8) * 64 + col];
            float v11 = base[(k0 + 9) * 64 + col];
            if (s == 0) { sW1[idx].x = packh(v00, v01); sW1[idx].y = packh(v10, v11); }
            else        { sW1[idx].z = packh(v00, v01); sW1[idx].w = packh(v10, v11); }
        }
    }
    for (int idx = threadIdx.x; idx < 2048; idx += blockDim.x) {
        int lanei = idx & 31, half = (idx >> 5) & 1, j2 = (idx >> 6) & 3, e = idx >> 8;
        int cc = lanei & 3, nn = lanei >> 2;
        int col = 8 * j2 + nn;
        const float* base = W2 + (size_t)e * 64 * 32;
        uint4 outv;
        #pragma unroll
        for (int t = 0; t < 2; t++) {
            int s2 = 2 * half + t;
            int k0 = 16 * s2 + 2 * cc;
            float v00 = base[(k0    ) * 32 + col];
            float v01 = base[(k0 + 1) * 32 + col];
            float v10 = base[(k0 + 8) * 32 + col];
            float v11 = base[(k0 + 9) * 32 + col];
            if (t == 0) { outv.x = packh(v00, v01); outv.y = packh(v10, v11); }
            else        { outv.z = packh(v00, v01); outv.w = packh(v10, v11); }
        }
        sW2[idx] = outv;
    }
    // L3 B-fragments: B[32,8] with col 0 = w3, cols 1..7 = 0 (nonzero only for nn==0).
    for (int idx = threadIdx.x; idx < 256; idx += blockDim.x) {
        int lanei = idx & 31, e = idx >> 5;
        int cc = lanei & 3, nn = lanei >> 2;
        uint4 v = make_uint4(0u, 0u, 0u, 0u);
        if (nn == 0) {
            const float* w3 = W3 + e * 32;
            v.x = packh(w3[2 * cc],      w3[2 * cc + 1]);
            v.y = packh(w3[2 * cc + 8],  w3[2 * cc + 9]);
            v.z = packh(w3[2 * cc + 16], w3[2 * cc + 17]);
            v.w = packh(w3[2 * cc + 24], w3[2 * cc + 25]);
        }
        sW3f[idx] = v;
    }
    for (int idx = threadIdx.x; idx < 256; idx += blockDim.x) {
        int cc = idx & 3, j = (idx >> 2) & 7, e = idx >> 5;
        int col = 8 * j + 2 * cc;
        sB1h[idx] = packh(b1[e * 64 + col], b1[e * 64 + col + 1]);
    }
    for (int idx = threadIdx.x; idx < 128; idx += blockDim.x) {
        int cc = idx & 3, j2 = (idx >> 2) & 3, e = idx >> 4;
        int col = 8 * j2 + 2 * cc;
        sB2h[idx] = packh(b2[e * 32 + col], b2[e * 32 + col + 1]);
    }
    if (threadIdx.x < 8) sB3h[threadIdx.x] = packh(b3[threadIdx.x], b3[threadIdx.x]);
    __syncthreads();

    const int lane = threadIdx.x & 31;
    const int c = lane & 3;       // quad column index
    const int rq = lane >> 2;     // row within 8-row group
    const int warp_global = blockIdx.x * 8 + (threadIdx.x >> 5);
    const int nwarps = gridDim.x * 8;

    for (int tile = warp_global; tile < NT32; tile += nwarps) {
        const int rowbase = tile << 5;

        // ---- load x A-fragments for 2 subtiles (f32 -> f16x2 on the fly) ----
        uint32_t xa[2][2][4];
        #pragma unroll
        for (int r = 0; r < 2; r++) {
            const float* xr0 = x + (size_t)(rowbase + r * 16 + rq) * 32;
            const float* xr1 = xr0 + 8 * 32;
            #pragma unroll
            for (int s = 0; s < 2; s++) {
                const int col = 16 * s + 2 * c;
                float2 v00 = *reinterpret_cast<const float2*>(xr0 + col);
                float2 v10 = *reinterpret_cast<const float2*>(xr1 + col);
                float2 v01 = *reinterpret_cast<const float2*>(xr0 + col + 8);
                float2 v11 = *reinterpret_cast<const float2*>(xr1 + col + 8);
                xa[r][s][0] = packh(v00.x, v00.y);
                xa[r][s][1] = packh(v10.x, v10.y);
                xa[r][s][2] = packh(v01.x, v01.y);
                xa[r][s][3] = packh(v11.x, v11.y);
            }
        }

        float oa[2][2];
        oa[0][0] = oa[0][1] = oa[1][0] = oa[1][1] = 0.f;

        #pragma unroll 1
        for (int e = 0; e < NUM_E; e++) {
            // ---- layer 1: [32,32] @ [32,64]; chain-start mma reads bias via C operand ----
            uint32_t ha[2][4][4];
            const uint4* w1e = sW1 + e * 256 + lane;
            #pragma unroll
            for (int j = 0; j < 8; j++) {
                uint4 B = w1e[j * 32];
                uint32_t bb = sB1h[e * 32 + j * 4 + c];
                const int s2 = j >> 1, h = j & 1;
                #pragma unroll
                for (int r = 0; r < 2; r++) {
                    uint32_t d0, d1;
                    mma_f16_init(d0, d1, xa[r][0], B.x, B.y, bb, bb);
                    mma_f16(d0, d1, xa[r][1], B.z, B.w);
                    ha[r][s2][h * 2 + 0] = hrelu(d0);
                    ha[r][s2][h * 2 + 1] = hrelu(d1);
                }
            }

            // ---- layer 2: [32,64] @ [64,32]; outputs feed L3 A-fragments directly ----
            uint32_t la[2][2][4];   // [r][s3][frag]
            const uint4* w2e = sW2 + e * 256 + lane;
            #pragma unroll
            for (int j2 = 0; j2 < 4; j2++) {
                uint4 Ca = w2e[(j2 * 2 + 0) * 32];   // s2 = 0,1
                uint4 Cb = w2e[(j2 * 2 + 1) * 32];   // s2 = 2,3
                uint32_t bb2 = sB2h[e * 16 + j2 * 4 + c];
                const int s3 = j2 >> 1, h = j2 & 1;
                #pragma unroll
                for (int r = 0; r < 2; r++) {
                    uint32_t d0, d1;
                    mma_f16_init(d0, d1, ha[r][0], Ca.x, Ca.y, bb2, bb2);
                    mma_f16(d0, d1, ha[r][1], Ca.z, Ca.w);
                    mma_f16(d0, d1, ha[r][2], Cb.x, Cb.y);
                    mma_f16(d0, d1, ha[r][3], Cb.z, Cb.w);
                    la[r][s3][h * 2 + 0] = hrelu(d0);
                    la[r][s3][h * 2 + 1] = hrelu(d1);
                }
            }

            // ---- layer 3 as HMMA: z = relu(h2) @ [w3 | 0...]; z in lo half of D regs ----
            uint4 W3v = sW3f[e * 32 + lane];
            uint32_t b3h = sB3h[e];
            #pragma unroll
            for (int r = 0; r < 2; r++) {
                uint32_t d0, d1;
                mma_f16_init(d0, d1, la[r][0], W3v.x, W3v.y, b3h, b3h);
                mma_f16(d0, d1, la[r][1], W3v.z, W3v.w);
                // d0.lo = z(row rq), d1.lo = z(row rq+8); valid where c==0, others harmless
                float z0 = __low2float(*reinterpret_cast<__half2*>(&d0));
                float z1 = __low2float(*reinterpret_cast<__half2*>(&d1));
                float s0 = 1.f / (1.f + __expf(-z0));
                float s1 = 1.f / (1.f + __expf(-z1));
                oa[r][0] += s0 * probs[(size_t)(rowbase + r * 16 + rq) * NUM_E + e];
                oa[r][1] += s1 * probs[(size_t)(rowbase + r * 16 + 8 + rq) * NUM_E + e];
            }
        }

        if (c == 0) {
            #pragma unroll
            for (int r = 0; r < 2; r++) {
                out[rowbase + r * 16 + rq]     = oa[r][0];
                out[rowbase + r * 16 + 8 + rq] = oa[r][1];
            }
        }
    }
}

extern "C" void kernel_launch(void* const* d_in, const int* in_sizes, int n_in,
                              void* d_out, int out_size) {
    const float* x     = (const float*)d_in[0];
    const float* probs = (const float*)d_in[1];
    const float* W1    = (const float*)d_in[2];
    const float* b1    = (const float*)d_in[3];
    const float* W2    = (const float*)d_in[4];
    const float* b2    = (const float*)d_in[5];
    const float* W3    = (const float*)d_in[6];
    const float* b3    = (const float*)d_in[7];
    float* out = (float*)d_out;

    const int B    = in_sizes[0] / 32;
    const int NT32 = B / 32;   // 16384 warp-tiles of 32 rows

    cudaFuncSetAttribute(moe_kernel, cudaFuncAttributeMaxDynamicSharedMemorySize, SMEM_BYTES);
    cudaFuncSetAttribute(moe_kernel, cudaFuncAttributePreferredSharedMemoryCarveout, 100);

    // 296 persistent CTAs (2 per SM), 2368 warps striding over 16384 tiles
    moe_kernel<<<296, 256, SMEM_BYTES>>>(x, probs, W1, b1, W2, b2, W3, b3, out, NT32);
}